// round 4
// baseline (speedup 1.0000x reference)
#include <cuda_runtime.h>

#define NT 128

// XOR swizzle: logical (row, kc[float4-chunk]) -> float offset in a 64x64 tile (stride 64).
// perm(row) = (row ^ (row>>3)) & 15 spreads both row-strides 4 and 8 across all bank groups.
#define PERM(r) (((r) ^ ((r) >> 3)) & 15)
#define SWZ(r, kc) (((((r) << 4) + ((kc) ^ PERM(r)))) << 2)

// Packed fp32 FMA (Blackwell f32x2): acc.lo += a.lo*b.lo; acc.hi += a.hi*b.hi
#define FMA2(acc, a, b) asm("fma.rn.f32x2 %0, %1, %2, %0;" : "+l"(acc) : "l"(a), "l"(b))

__device__ __forceinline__ float fold(unsigned long long v) {
    return __uint_as_float((unsigned)v) + __uint_as_float((unsigned)(v >> 32));
}

// C(64x64) = A(64x64, row-major) @ B where BT holds B transposed (BT[j][k]).
// Thread computes rows i0..i0+3, cols j0..j0+7. k paired into f32x2 lanes.
__device__ __forceinline__ void mmT(const float* __restrict__ A,
                                    const float* __restrict__ BT,
                                    int i0, int j0,
                                    unsigned long long acc[4][8])
{
#pragma unroll
    for (int r = 0; r < 4; r++)
#pragma unroll
        for (int c = 0; c < 8; c++) acc[r][c] = 0ull;

#pragma unroll 4
    for (int kc = 0; kc < 16; kc++) {
        ulonglong2 a[4];
#pragma unroll
        for (int r = 0; r < 4; r++)
            a[r] = *(const ulonglong2*)(A + SWZ(i0 + r, kc));
#pragma unroll
        for (int c = 0; c < 8; c++) {
            ulonglong2 bv = *(const ulonglong2*)(BT + SWZ(j0 + c, kc));
#pragma unroll
            for (int r = 0; r < 4; r++) {
                FMA2(acc[r][c], a[r].x, bv.x);
                FMA2(acc[r][c], a[r].y, bv.y);
            }
        }
    }
}

__global__ __launch_bounds__(NT, 3) void pgcn_kernel(
    const float* __restrict__ device_obs,   // [B,63,14]
    const float* __restrict__ server_obs,   // [B,3]
    const float* __restrict__ adjacency,    // [B,64,64]
    const float* __restrict__ W_dev, const float* __restrict__ b_dev,
    const float* __restrict__ W_srv, const float* __restrict__ b_srv,
    const float* __restrict__ W1, const float* __restrict__ b1,
    const float* __restrict__ W2, const float* __restrict__ b2,
    const float* __restrict__ W3, const float* __restrict__ b3,
    const float* __restrict__ Wf1, const float* __restrict__ bf1,
    const float* __restrict__ Wf2, const float* __restrict__ bf2,
    float* __restrict__ out)                // [B,63]
{
    extern __shared__ float sm[];
    float* s_adj  = sm;             // 4096: adj_norm (row-major); after layer 3: h row-major
    float* s_hT   = sm + 4096;      // 4096: h transposed (B operand of adj@h)
    float* s_t    = sm + 8192;      // 4096: t = adj@h row-major; initially obs staging
    float* s_w    = sm + 12288;     // 4096: staged B-transposed weights; initially Wdev/Wsrv
    float* s_d    = sm + 16384;     // 64
    float* s_mean = s_d + 64;       // 64
    float* s_sh   = s_mean + 64;    // 128

    const int b   = blockIdx.x;
    const int tid = threadIdx.x;
    const int tc  = tid & 7;        // col group 0..7
    const int tr  = tid >> 3;       // row group 0..15
    const int i0  = tr << 2;
    const int j0  = tc << 3;

    // ---- Phase 1: load adjacency (swizzled), obs -> s_t, embed weights -> s_w ----
    {
        const float4* adjg = (const float4*)(adjacency + (size_t)b * 4096);
#pragma unroll
        for (int idx = tid; idx < 1024; idx += NT) {
            int row = idx >> 4, kc = idx & 15;
            *(float4*)(s_adj + SWZ(row, kc)) = adjg[idx];
        }
        const float* dob = device_obs + (size_t)b * 882;
        for (int idx = tid; idx < 882; idx += NT) s_t[idx] = dob[idx];
        // s_w staging: [0:896) W_dev, [896:960) b_dev, [960:1152) W_srv, [1152:1216) b_srv
        for (int idx = tid; idx < 896;  idx += NT) s_w[idx]        = W_dev[idx];
        for (int idx = tid; idx < 64;   idx += NT) s_w[896 + idx]  = b_dev[idx];
        for (int idx = tid; idx < 192;  idx += NT) s_w[960 + idx]  = W_srv[idx];
        for (int idx = tid; idx < 64;   idx += NT) s_w[1152 + idx] = b_srv[idx];
    }
    const float so0 = server_obs[b * 3 + 0];
    const float so1 = server_obs[b * 3 + 1];
    const float so2 = server_obs[b * 3 + 2];
    __syncthreads();

    // ---- degree -> d^-1/2 ----
    if (tid < 64) {
        float s = 0.0f;
#pragma unroll
        for (int kc = 0; kc < 16; kc++) {
            float4 v = *(const float4*)(s_adj + SWZ(tid, kc));
            s += (v.x + v.y) + (v.z + v.w);
        }
        s_d[tid] = rsqrtf(fmaxf(s, 1.0f));
    }
    __syncthreads();

    // ---- normalize adjacency (swizzled in place) ----
#pragma unroll
    for (int idx = tid; idx < 1024; idx += NT) {
        int row = idx >> 4, kc = idx & 15;
        float di = s_d[row];
        float* p = s_adj + SWZ(row, kc);
        float4 v = *(float4*)p;
        int j = kc << 2;
        v.x *= di * s_d[j + 0];
        v.y *= di * s_d[j + 1];
        v.z *= di * s_d[j + 2];
        v.w *= di * s_d[j + 3];
        *(float4*)p = v;
    }

    // ---- build x^T into s_hT: xT[j][i] ----
    for (int idx = tid; idx < 1024; idx += NT) {
        int j = idx & 63, i4 = idx >> 6;
        float val[4];
#pragma unroll
        for (int q = 0; q < 4; q++) {
            int i = (i4 << 2) + q;
            float acc;
            if (i < 63) {
                acc = s_w[896 + j];
                const float* o = s_t + i * 14;
#pragma unroll
                for (int k = 0; k < 14; k++)
                    acc = fmaf(o[k], s_w[k * 64 + j], acc);
            } else {
                acc = s_w[1152 + j];
                acc = fmaf(so0, s_w[960 + j], acc);
                acc = fmaf(so1, s_w[1024 + j], acc);
                acc = fmaf(so2, s_w[1088 + j], acc);
            }
            val[q] = fmaxf(acc, 0.0f);
        }
        *(float4*)(s_hT + SWZ(j, i4)) = make_float4(val[0], val[1], val[2], val[3]);
    }
    __syncthreads();

    // ---- 3 GCN layers ----
    const float* Ws[3] = {W1, W2, W3};
    const float* bs[3] = {b1, b2, b3};
#pragma unroll 1
    for (int L = 0; L < 3; L++) {
        // stage W^T into s_w (read row-major coalesced, scatter-transpose)
        const float* Wg = Ws[L];
        for (int idx = tid; idx < 1024; idx += NT) {
            int k = idx >> 4, jc = idx & 15;
            float4 w = *(const float4*)(Wg + k * 64 + (jc << 2));
            int kc = k >> 2, e = k & 3;
            s_w[SWZ((jc << 2) + 0, kc) + e] = w.x;
            s_w[SWZ((jc << 2) + 1, kc) + e] = w.y;
            s_w[SWZ((jc << 2) + 2, kc) + e] = w.z;
            s_w[SWZ((jc << 2) + 3, kc) + e] = w.w;
        }
        __syncthreads();

        // GEMM1: t = adj_norm @ h  (B operand = s_hT), write t row-major
        {
            unsigned long long acc[4][8];
            mmT(s_adj, s_hT, i0, j0, acc);
#pragma unroll
            for (int r = 0; r < 4; r++)
#pragma unroll
                for (int cc = 0; cc < 2; cc++) {
                    float4 v = make_float4(fold(acc[r][cc * 4 + 0]), fold(acc[r][cc * 4 + 1]),
                                           fold(acc[r][cc * 4 + 2]), fold(acc[r][cc * 4 + 3]));
                    *(float4*)(s_t + SWZ(i0 + r, (j0 >> 2) + cc)) = v;
                }
        }
        __syncthreads();

        // GEMM2: h' = relu(t @ W + b), write h'^T (and row-major copy into s_adj on last layer)
        {
            unsigned long long acc[4][8];
            mmT(s_t, s_w, i0, j0, acc);
            float bb[8];
            *(float4*)&bb[0] = *(const float4*)(bs[L] + j0);
            *(float4*)&bb[4] = *(const float4*)(bs[L] + j0 + 4);
#pragma unroll
            for (int c = 0; c < 8; c++) {
                float u0 = fmaxf(fold(acc[0][c]) + bb[c], 0.0f);
                float u1 = fmaxf(fold(acc[1][c]) + bb[c], 0.0f);
                float u2 = fmaxf(fold(acc[2][c]) + bb[c], 0.0f);
                float u3 = fmaxf(fold(acc[3][c]) + bb[c], 0.0f);
                *(float4*)(s_hT + SWZ(j0 + c, tr)) = make_float4(u0, u1, u2, u3);
            }
            if (L == 2) {
#pragma unroll
                for (int r = 0; r < 4; r++)
#pragma unroll
                    for (int cc = 0; cc < 2; cc++) {
                        float4 v;
                        v.x = fmaxf(fold(acc[r][cc * 4 + 0]) + bb[cc * 4 + 0], 0.0f);
                        v.y = fmaxf(fold(acc[r][cc * 4 + 1]) + bb[cc * 4 + 1], 0.0f);
                        v.z = fmaxf(fold(acc[r][cc * 4 + 2]) + bb[cc * 4 + 2], 0.0f);
                        v.w = fmaxf(fold(acc[r][cc * 4 + 3]) + bb[cc * 4 + 3], 0.0f);
                        *(float4*)(s_adj + SWZ(i0 + r, (j0 >> 2) + cc)) = v;
                    }
            }
        }
        __syncthreads();
    }
    // Now: s_adj = h row-major, s_hT = h transposed.

    // ---- dev_mean (row sums of h^T, minus server col) ----
    if (tid < 64) {
        float s = 0.0f;
#pragma unroll
        for (int kc = 0; kc < 16; kc++) {
            float4 v = *(const float4*)(s_hT + SWZ(tid, kc));
            s += (v.x + v.y) + (v.z + v.w);
        }
        s -= s_hT[SWZ(tid, 15) + 3];   // subtract h[63][tid]
        s_mean[tid] = s * (1.0f / 63.0f);
    }
    __syncthreads();

    // ---- shared head vector: bf1 + dev_mean @ Wf1[64:128] + server @ Wf1[128:192] ----
    {
        float acc = bf1[tid];
#pragma unroll 4
        for (int k = 0; k < 64; k++) {
            float srv = s_adj[SWZ(63, k >> 2) + (k & 3)];
            acc = fmaf(s_mean[k], Wf1[(64 + k) * 128 + tid], acc);
            acc = fmaf(srv, Wf1[(128 + k) * 128 + tid], acc);
        }
        s_sh[tid] = acc;
    }

    // ---- head: 2 chunks of u = relu(h @ Wf1_chunk + sh); out += u @ Wf2_chunk ----
    float outacc[4] = {0.0f, 0.0f, 0.0f, 0.0f};
#pragma unroll 1
    for (int c2 = 0; c2 < 2; c2++) {
        // stage Wf1 chunk transposed into s_w
        for (int idx = tid; idx < 1024; idx += NT) {
            int k = idx >> 4, jc = idx & 15;
            float4 w = *(const float4*)(Wf1 + k * 128 + c2 * 64 + (jc << 2));
            int kc = k >> 2, e = k & 3;
            s_w[SWZ((jc << 2) + 0, kc) + e] = w.x;
            s_w[SWZ((jc << 2) + 1, kc) + e] = w.y;
            s_w[SWZ((jc << 2) + 2, kc) + e] = w.z;
            s_w[SWZ((jc << 2) + 3, kc) + e] = w.w;
        }
        __syncthreads();

        unsigned long long acc[4][8];
        mmT(s_adj, s_w, i0, j0, acc);

        float sv[8], w2[8];
        *(float4*)&sv[0] = *(const float4*)(s_sh + c2 * 64 + j0);
        *(float4*)&sv[4] = *(const float4*)(s_sh + c2 * 64 + j0 + 4);
        *(float4*)&w2[0] = *(const float4*)(Wf2 + c2 * 64 + j0);
        *(float4*)&w2[4] = *(const float4*)(Wf2 + c2 * 64 + j0 + 4);

        float part[4] = {0.0f, 0.0f, 0.0f, 0.0f};
#pragma unroll
        for (int c = 0; c < 8; c++) {
#pragma unroll
            for (int r = 0; r < 4; r++)
                part[r] = fmaf(fmaxf(fold(acc[r][c]) + sv[c], 0.0f), w2[c], part[r]);
        }
#pragma unroll
        for (int off = 4; off > 0; off >>= 1)
#pragma unroll
            for (int r = 0; r < 4; r++)
                part[r] += __shfl_down_sync(0xffffffffu, part[r], off, 8);
        if (tc == 0)
#pragma unroll
            for (int r = 0; r < 4; r++) outacc[r] += part[r];
        __syncthreads();
    }

    // ---- write output ----
    if (tc == 0) {
        float bias = bf2[0];
#pragma unroll
        for (int r = 0; r < 4; r++) {
            int i = i0 + r;
            if (i < 63) out[(size_t)b * 63 + i] = outacc[r] + bias;
        }
    }
}

extern "C" void kernel_launch(void* const* d_in, const int* in_sizes, int n_in,
                              void* d_out, int out_size)
{
    const float* device_obs = (const float*)d_in[0];
    const float* server_obs = (const float*)d_in[1];
    const float* adjacency  = (const float*)d_in[2];
    const float* W_dev = (const float*)d_in[3];
    const float* b_dev = (const float*)d_in[4];
    const float* W_srv = (const float*)d_in[5];
    const float* b_srv = (const float*)d_in[6];
    const float* W1 = (const float*)d_in[7];
    const float* b1 = (const float*)d_in[8];
    const float* W2 = (const float*)d_in[9];
    const float* b2 = (const float*)d_in[10];
    const float* W3 = (const float*)d_in[11];
    const float* b3 = (const float*)d_in[12];
    const float* Wf1 = (const float*)d_in[13];
    const float* bf1 = (const float*)d_in[14];
    const float* Wf2 = (const float*)d_in[15];
    const float* bf2 = (const float*)d_in[16];

    const int B = in_sizes[0] / (63 * 14);
    const size_t smem = (4 * 4096 + 64 + 64 + 128) * sizeof(float);
    cudaFuncSetAttribute(pgcn_kernel, cudaFuncAttributeMaxDynamicSharedMemorySize, (int)smem);
    pgcn_kernel<<<B, NT, smem>>>(
        device_obs, server_obs, adjacency,
        W_dev, b_dev, W_srv, b_srv,
        W1, b1, W2, b2, W3, b3,
        Wf1, bf1, Wf2, bf2,
        (float*)d_out);
}

// round 5
// speedup vs baseline: 1.8484x; 1.8484x over previous
#include <cuda_runtime.h>

#define NT 128
#define ST 72   // row stride (floats): bank = (8*row + col) % 32 -> conflict-free frags

// fp32 -> tf32 bit pattern (stored as float)
__device__ __forceinline__ float f2tf(float x) {
    unsigned r;
    asm("cvt.rna.tf32.f32 %0, %1;" : "=r"(r) : "f"(x));
    return __uint_as_float(r);
}

__device__ __forceinline__ void mma8(float* c, unsigned a0, unsigned a1, unsigned a2, unsigned a3,
                                     unsigned b0, unsigned b1) {
    asm("mma.sync.aligned.m16n8k8.row.col.f32.tf32.tf32.f32 "
        "{%0,%1,%2,%3}, {%4,%5,%6,%7}, {%8,%9}, {%0,%1,%2,%3};"
        : "+f"(c[0]), "+f"(c[1]), "+f"(c[2]), "+f"(c[3])
        : "r"(a0), "r"(a1), "r"(a2), "r"(a3), "r"(b0), "r"(b1));
}

// C(64x64) = A(64x64) @ B(64x64); A,B row-major stride ST, tf32 bits.
// Warp w computes rows 16w..16w+15 (C tiles: 8 n-tiles of 16x8).
// A frag: a0=(gid,tig) a1=(gid+8,tig) a2=(gid,tig+4) a3=(gid+8,tig+4)  [cols +8*ks]
// B frag: b0=(k=tig, n=gid) b1=(k=tig+4, n=gid)                        [k +8*ks, n +8*nt]
__device__ __forceinline__ void gemm64(const float* __restrict__ A,
                                       const float* __restrict__ B,
                                       int w, int gid, int tig, float c[8][4]) {
#pragma unroll
    for (int nt = 0; nt < 8; nt++)
#pragma unroll
        for (int q = 0; q < 4; q++) c[nt][q] = 0.0f;

    const float* Ar0 = A + (w * 16 + gid) * ST + tig;
    const float* Ar8 = Ar0 + 8 * ST;
    const float* Bb  = B + tig * ST + gid;
#pragma unroll
    for (int ks = 0; ks < 8; ks++) {
        unsigned a0 = __float_as_uint(Ar0[8 * ks]);
        unsigned a1 = __float_as_uint(Ar8[8 * ks]);
        unsigned a2 = __float_as_uint(Ar0[8 * ks + 4]);
        unsigned a3 = __float_as_uint(Ar8[8 * ks + 4]);
        const float* Bk = Bb + (8 * ks) * ST;
#pragma unroll
        for (int nt = 0; nt < 8; nt++) {
            unsigned b0 = __float_as_uint(Bk[8 * nt]);
            unsigned b1 = __float_as_uint(Bk[4 * ST + 8 * nt]);
            mma8(c[nt], a0, a1, a2, a3, b0, b1);
        }
    }
}

__global__ __launch_bounds__(NT, 3) void pgcn_kernel(
    const float* __restrict__ device_obs,   // [B,63,14]
    const float* __restrict__ server_obs,   // [B,3]
    const float* __restrict__ adjacency,    // [B,64,64]
    const float* __restrict__ W_dev, const float* __restrict__ b_dev,
    const float* __restrict__ W_srv, const float* __restrict__ b_srv,
    const float* __restrict__ W1, const float* __restrict__ b1,
    const float* __restrict__ W2, const float* __restrict__ b2,
    const float* __restrict__ W3, const float* __restrict__ b3,
    const float* __restrict__ Wf1, const float* __restrict__ bf1,
    const float* __restrict__ Wf2, const float* __restrict__ bf2,
    float* __restrict__ out)                // [B,63]
{
    extern __shared__ float sm[];
    float* s_adj  = sm;                 // [64][ST] adj_norm (tf32)
    float* s_h    = sm + 4608;          // [64][ST] node features (tf32)
    float* s_t    = sm + 9216;          // [64][ST] temp / obs+embed-weight staging / Wf1 chunk
    float* s_w    = sm + 13824;         // [64][ST] staged layer weights (tf32)
    float* s_d    = sm + 18432;         // 64
    float* s_mean = s_d + 64;           // 64
    float* s_sh   = s_mean + 64;        // 128 (fp32)
    float* s_w2   = s_sh + 128;         // 128 (fp32) Wf2
    float* s_b    = s_w2 + 128;         // 64  (fp32) layer bias

    const int b    = blockIdx.x;
    const int tid  = threadIdx.x;
    const int w    = tid >> 5;
    const int lane = tid & 31;
    const int gid  = lane >> 2;
    const int tig  = lane & 3;

    // ---- P0: global -> shared staging ----
    {
        const float4* adjg = (const float4*)(adjacency + (size_t)b * 4096);
#pragma unroll
        for (int idx = tid; idx < 1024; idx += NT) {
            int row = idx >> 4, jc = (idx & 15) << 2;
            *(float4*)&s_adj[row * ST + jc] = adjg[idx];
        }
        const float* dob = device_obs + (size_t)b * 882;
        for (int idx = tid; idx < 882; idx += NT) s_t[idx] = dob[idx];
        for (int idx = tid; idx < 896; idx += NT) s_t[1024 + idx] = W_dev[idx];
        if (tid < 64)  s_t[1920 + tid] = b_dev[tid];
        for (int idx = tid; idx < 192; idx += NT) s_t[1984 + idx] = W_srv[idx];
        if (tid < 64)  s_t[2176 + tid] = b_srv[tid];
    }
    const float so0 = server_obs[b * 3 + 0];
    const float so1 = server_obs[b * 3 + 1];
    const float so2 = server_obs[b * 3 + 2];
    const float bf2v = bf2[0];
    __syncthreads();

    // ---- degree -> d^-1/2 ----
    if (tid < 64) {
        float s = 0.0f;
#pragma unroll
        for (int jc = 0; jc < 16; jc++) {
            float4 v = *(const float4*)&s_adj[tid * ST + (jc << 2)];
            s += (v.x + v.y) + (v.z + v.w);
        }
        s_d[tid] = rsqrtf(fmaxf(s, 1.0f));
    }
    __syncthreads();

    // ---- normalize adjacency, convert to tf32 ----
#pragma unroll
    for (int idx = tid; idx < 1024; idx += NT) {
        int row = idx >> 4, jc = (idx & 15) << 2;
        float di = s_d[row];
        float* p = &s_adj[row * ST + jc];
        float4 v = *(float4*)p;
        v.x = f2tf(v.x * di * s_d[jc + 0]);
        v.y = f2tf(v.y * di * s_d[jc + 1]);
        v.z = f2tf(v.z * di * s_d[jc + 2]);
        v.w = f2tf(v.w * di * s_d[jc + 3]);
        *(float4*)p = v;
    }

    // ---- embed: x -> s_h (tf32, row-major) ----
    {
        const float* s_obs  = s_t;
        const float* s_wdev = s_t + 1024;
        const float* s_bdev = s_t + 1920;
        const float* s_wsrv = s_t + 1984;
        const float* s_bsrv = s_t + 2176;
        for (int idx = tid; idx < 4096; idx += NT) {
            int i = idx >> 6, j = idx & 63;
            float acc;
            if (i < 63) {
                acc = s_bdev[j];
                const float* o = s_obs + i * 14;
#pragma unroll
                for (int k = 0; k < 14; k++)
                    acc = fmaf(o[k], s_wdev[k * 64 + j], acc);
            } else {
                acc = s_bsrv[j];
                acc = fmaf(so0, s_wsrv[j], acc);
                acc = fmaf(so1, s_wsrv[64 + j], acc);
                acc = fmaf(so2, s_wsrv[128 + j], acc);
            }
            s_h[i * ST + j] = f2tf(fmaxf(acc, 0.0f));
        }
    }
    __syncthreads();

    // ---- 3 GCN layers ----
    const float* Ws[3]  = {W1, W2, W3};
    const float* bsv[3] = {b1, b2, b3};
    const int r0 = w * 16 + gid, r1 = r0 + 8, cb = tig << 1;
#pragma unroll 1
    for (int L = 0; L < 3; L++) {
        // stage W_L (tf32) + bias
        const float* Wg = Ws[L];
        for (int idx = tid; idx < 1024; idx += NT) {
            int k = idx >> 4, jc = (idx & 15) << 2;
            float4 v = *(const float4*)(Wg + k * 64 + jc);
            v.x = f2tf(v.x); v.y = f2tf(v.y); v.z = f2tf(v.z); v.w = f2tf(v.w);
            *(float4*)&s_w[k * ST + jc] = v;
        }
        if (tid < 64) s_b[tid] = bsv[L][tid];

        // GEMM1: t = adj_norm @ h
        {
            float c[8][4];
            gemm64(s_adj, s_h, w, gid, tig, c);
#pragma unroll
            for (int nt = 0; nt < 8; nt++) {
                *(float2*)&s_t[r0 * ST + (nt << 3) + cb] = make_float2(f2tf(c[nt][0]), f2tf(c[nt][1]));
                *(float2*)&s_t[r1 * ST + (nt << 3) + cb] = make_float2(f2tf(c[nt][2]), f2tf(c[nt][3]));
            }
        }
        __syncthreads();

        // GEMM2: h = relu(t @ W + b)
        {
            float c[8][4];
            gemm64(s_t, s_w, w, gid, tig, c);
#pragma unroll
            for (int nt = 0; nt < 8; nt++) {
                float2 bb = *(const float2*)&s_b[(nt << 3) + cb];
                *(float2*)&s_h[r0 * ST + (nt << 3) + cb] =
                    make_float2(f2tf(fmaxf(c[nt][0] + bb.x, 0.0f)), f2tf(fmaxf(c[nt][1] + bb.y, 0.0f)));
                *(float2*)&s_h[r1 * ST + (nt << 3) + cb] =
                    make_float2(f2tf(fmaxf(c[nt][2] + bb.x, 0.0f)), f2tf(fmaxf(c[nt][3] + bb.y, 0.0f)));
            }
        }
        __syncthreads();
    }

    // ---- head: dev_mean + Wf2 staging ----
    if (tid < 64) {
        float s = 0.0f;
#pragma unroll 7
        for (int i = 0; i < 63; i++) s += s_h[i * ST + tid];
        s_mean[tid] = s * (1.0f / 63.0f);
    } else {
        int k = tid - 64;
        s_w2[k] = Wf2[k];
        s_w2[k + 64] = Wf2[k + 64];
    }
    __syncthreads();

    // ---- shared head vector (fp32): bf1 + mean @ Wf1[64:128] + srv @ Wf1[128:192] ----
    {
        float acc = bf1[tid];
        const float* srv = &s_h[63 * ST];
#pragma unroll 4
        for (int k = 0; k < 64; k++) {
            acc = fmaf(s_mean[k], Wf1[(64 + k) * 128 + tid], acc);
            acc = fmaf(srv[k],    Wf1[(128 + k) * 128 + tid], acc);
        }
        s_sh[tid] = acc;
    }
    __syncthreads();

    // ---- head GEMM in two 64-col chunks ----
    float p0 = 0.0f, p1 = 0.0f;
#pragma unroll 1
    for (int c2 = 0; c2 < 2; c2++) {
        // stage Wf1 chunk (tf32) into s_t
        for (int idx = tid; idx < 1024; idx += NT) {
            int k = idx >> 4, jc = (idx & 15) << 2;
            float4 v = *(const float4*)(Wf1 + k * 128 + (c2 << 6) + jc);
            v.x = f2tf(v.x); v.y = f2tf(v.y); v.z = f2tf(v.z); v.w = f2tf(v.w);
            *(float4*)&s_t[k * ST + jc] = v;
        }
        __syncthreads();

        float c[8][4];
        gemm64(s_h, s_t, w, gid, tig, c);
#pragma unroll
        for (int nt = 0; nt < 8; nt++) {
            int col = (c2 << 6) + (nt << 3) + cb;
            float2 sh = *(const float2*)&s_sh[col];
            float2 w2 = *(const float2*)&s_w2[col];
            p0 = fmaf(fmaxf(c[nt][0] + sh.x, 0.0f), w2.x, p0);
            p0 = fmaf(fmaxf(c[nt][1] + sh.y, 0.0f), w2.y, p0);
            p1 = fmaf(fmaxf(c[nt][2] + sh.x, 0.0f), w2.x, p1);
            p1 = fmaf(fmaxf(c[nt][3] + sh.y, 0.0f), w2.y, p1);
        }
        __syncthreads();
    }

    // reduce across the 4 lanes of each group (columns) and write
    p0 += __shfl_xor_sync(0xffffffffu, p0, 1, 4);
    p0 += __shfl_xor_sync(0xffffffffu, p0, 2, 4);
    p1 += __shfl_xor_sync(0xffffffffu, p1, 1, 4);
    p1 += __shfl_xor_sync(0xffffffffu, p1, 2, 4);
    if (tig == 0) {
        out[(size_t)b * 63 + r0] = p0 + bf2v;          // r0 <= 55, always valid
        if (r1 < 63) out[(size_t)b * 63 + r1] = p1 + bf2v;
    }
}

extern "C" void kernel_launch(void* const* d_in, const int* in_sizes, int n_in,
                              void* d_out, int out_size)
{
    const float* device_obs = (const float*)d_in[0];
    const float* server_obs = (const float*)d_in[1];
    const float* adjacency  = (const float*)d_in[2];
    const float* W_dev = (const float*)d_in[3];
    const float* b_dev = (const float*)d_in[4];
    const float* W_srv = (const float*)d_in[5];
    const float* b_srv = (const float*)d_in[6];
    const float* W1 = (const float*)d_in[7];
    const float* b1 = (const float*)d_in[8];
    const float* W2 = (const float*)d_in[9];
    const float* b2 = (const float*)d_in[10];
    const float* W3 = (const float*)d_in[11];
    const float* b3 = (const float*)d_in[12];
    const float* Wf1 = (const float*)d_in[13];
    const float* bf1 = (const float*)d_in[14];
    const float* Wf2 = (const float*)d_in[15];
    const float* bf2 = (const float*)d_in[16];

    const int B = in_sizes[0] / (63 * 14);
    const size_t smem = (4 * 64 * ST + 64 + 64 + 128 + 128 + 64) * sizeof(float);
    cudaFuncSetAttribute(pgcn_kernel, cudaFuncAttributeMaxDynamicSharedMemorySize, (int)smem);
    pgcn_kernel<<<B, NT, smem>>>(
        device_obs, server_obs, adjacency,
        W_dev, b_dev, W_srv, b_srv,
        W1, b1, W2, b2, W3, b3,
        Wf1, bf1, Wf2, bf2,
        (float*)d_out);
}

// round 6
// speedup vs baseline: 2.2832x; 1.2353x over previous
#include <cuda_runtime.h>

#define NT 128
#define ST 72   // 72 ≡ 8 (mod 32): with col^=(row&4) swizzle all frag accesses are conflict-free

__device__ __forceinline__ float f2tf(float x) {
    unsigned r;
    asm("cvt.rna.tf32.f32 %0, %1;" : "=r"(r) : "f"(x));
    return __uint_as_float(r);
}

__device__ __forceinline__ void mma8(float* c, unsigned a0, unsigned a1, unsigned a2, unsigned a3,
                                     unsigned b0, unsigned b1) {
    asm("mma.sync.aligned.m16n8k8.row.col.f32.tf32.tf32.f32 "
        "{%0,%1,%2,%3}, {%4,%5,%6,%7}, {%8,%9}, {%0,%1,%2,%3};"
        : "+f"(c[0]), "+f"(c[1]), "+f"(c[2]), "+f"(c[3])
        : "r"(a0), "r"(a1), "r"(a2), "r"(a3), "r"(b0), "r"(b1));
}

// C(16w..16w+15, 0..63) += A(rows from smem, swizzled) @ B(smem, swizzled)
__device__ __forceinline__ void gemm_ss(const float* __restrict__ A, const float* __restrict__ B,
                                        int rb, int gid, int tig, float c[8][4]) {
#pragma unroll
    for (int nt = 0; nt < 8; nt++)
#pragma unroll
        for (int q = 0; q < 4; q++) c[nt][q] = 0.0f;

    const int x4 = gid & 4;
    const int ca = tig ^ x4;
    const float* A0 = A + (rb + gid) * ST;
    const float* A1 = A0 + 8 * ST;
    const float* B0 = B + tig * ST;           // b0 rows: bit2=0, no col xor
    const float* B1 = B + (tig + 4) * ST;     // b1 rows: bit2=1, col^4
    const int g0 = gid, g1 = gid ^ 4;
#pragma unroll
    for (int ks = 0; ks < 8; ks++) {
        unsigned a0 = __float_as_uint(A0[ca + 8 * ks]);
        unsigned a1 = __float_as_uint(A1[ca + 8 * ks]);
        unsigned a2 = __float_as_uint(A0[(ca ^ 4) + 8 * ks]);
        unsigned a3 = __float_as_uint(A1[(ca ^ 4) + 8 * ks]);
        const float* b0r = B0 + 8 * ks * ST;
        const float* b1r = B1 + 8 * ks * ST;
#pragma unroll
        for (int nt = 0; nt < 8; nt++) {
            unsigned b0 = __float_as_uint(b0r[g0 + 8 * nt]);
            unsigned b1 = __float_as_uint(b1r[g1 + 8 * nt]);
            mma8(c[nt], a0, a1, a2, a3, b0, b1);
        }
    }
}

// Same but A-fragments live in registers (binary adjacency, cached once).
__device__ __forceinline__ void gemm_rs(const unsigned af[8][4], const float* __restrict__ B,
                                        int gid, int tig, float c[8][4]) {
#pragma unroll
    for (int nt = 0; nt < 8; nt++)
#pragma unroll
        for (int q = 0; q < 4; q++) c[nt][q] = 0.0f;

    const float* B0 = B + tig * ST;
    const float* B1 = B + (tig + 4) * ST;
    const int g0 = gid, g1 = gid ^ 4;
#pragma unroll
    for (int ks = 0; ks < 8; ks++) {
        const float* b0r = B0 + 8 * ks * ST;
        const float* b1r = B1 + 8 * ks * ST;
#pragma unroll
        for (int nt = 0; nt < 8; nt++) {
            unsigned b0 = __float_as_uint(b0r[g0 + 8 * nt]);
            unsigned b1 = __float_as_uint(b1r[g1 + 8 * nt]);
            mma8(c[nt], af[ks][0], af[ks][1], af[ks][2], af[ks][3], b0, b1);
        }
    }
}

// Stage a 64x64 weight block (row stride `stride`, col offset coff) into swizzled tf32 smem.
__device__ __forceinline__ void stage_w(float* dst, const float* __restrict__ src,
                                        int stride, int coff, int tid) {
    for (int idx = tid; idx < 1024; idx += NT) {
        int k = idx >> 4, jc = (idx & 15) << 2;
        float4 v = *(const float4*)(src + k * stride + coff + jc);
        v.x = f2tf(v.x); v.y = f2tf(v.y); v.z = f2tf(v.z); v.w = f2tf(v.w);
        *(float4*)&dst[k * ST + (jc ^ (k & 4))] = v;
    }
}

__global__ __launch_bounds__(NT, 4) void pgcn_kernel(
    const float* __restrict__ device_obs,   // [B,63,14]
    const float* __restrict__ server_obs,   // [B,3]
    const float* __restrict__ adjacency,    // [B,64,64] binary
    const float* __restrict__ W_dev, const float* __restrict__ b_dev,
    const float* __restrict__ W_srv, const float* __restrict__ b_srv,
    const float* __restrict__ W1, const float* __restrict__ b1,
    const float* __restrict__ W2, const float* __restrict__ b2,
    const float* __restrict__ W3, const float* __restrict__ b3,
    const float* __restrict__ Wf1, const float* __restrict__ bf1,
    const float* __restrict__ Wf2, const float* __restrict__ bf2,
    float* __restrict__ out)                // [B,63]
{
    extern __shared__ float sm[];
    float* s_h    = sm;                 // [64][ST] activations; row tails 64..66 hold b1,b2,b3
    float* s_w    = sm + 4608;          // [64][ST] staged weights (initially embed staging)
    float* s_aux  = sm + 9216;          // [64][ST] adjacency; later Wf1 chunk1
    float* s_d    = sm + 13824;         // 64
    float* s_mean = s_d + 64;           // 64
    float* s_sh   = s_mean + 64;        // 128
    float* s_w2   = s_sh + 128;         // 128

    const int b    = blockIdx.x;
    const int tid  = threadIdx.x;
    const int w    = tid >> 5;
    const int lane = tid & 31;
    const int gid  = lane >> 2;
    const int tig  = lane & 3;
    const int rb   = w << 4;
    const int r0   = rb + gid, r1 = r0 + 8;
    const int x4   = gid & 4;

    // ---- P0: stage everything ----
    {
        const float4* adjg = (const float4*)(adjacency + (size_t)b * 4096);
#pragma unroll
        for (int idx = tid; idx < 1024; idx += NT) {
            int row = idx >> 4, jc = (idx & 15) << 2;
            *(float4*)&s_aux[row * ST + (jc ^ (row & 4))] = adjg[idx];   // binary, tf32-exact
        }
        const float* dob = device_obs + (size_t)b * 882;
        for (int idx = tid; idx < 882; idx += NT) s_w[idx] = dob[idx];
        for (int idx = tid; idx < 896; idx += NT) s_w[896 + idx] = W_dev[idx];
        if (tid < 64) s_w[1792 + tid] = b_dev[tid];
        for (int idx = tid; idx < 192; idx += NT) s_w[1856 + idx] = W_srv[idx];
        if (tid < 64) s_w[2048 + tid] = b_srv[tid];
        if (tid < 64) {           // biases in s_h row tails (cols 64..66, never clobbered)
            s_h[tid * ST + 64] = b1[tid];
            s_h[tid * ST + 65] = b2[tid];
            s_h[tid * ST + 66] = b3[tid];
        }
        if (tid < 128) s_w2[tid] = Wf2[tid];
    }
    const float so0 = server_obs[b * 3 + 0];
    const float so1 = server_obs[b * 3 + 1];
    const float so2 = server_obs[b * 3 + 2];
    const float bf2v = bf2[0];
    __syncthreads();

    // ---- degree -> d^-1/2 (row sum invariant under col permutation) ----
    if (tid < 64) {
        float s = 0.0f;
#pragma unroll
        for (int jc = 0; jc < 16; jc++) {
            float4 v = *(const float4*)&s_aux[tid * ST + (jc << 2)];
            s += (v.x + v.y) + (v.z + v.w);
        }
        s_d[tid] = rsqrtf(fmaxf(s, 1.0f));
    }
    __syncthreads();

    // ---- embed: x -> s_h (tf32, swizzled) ----
    {
        const float* s_obs  = s_w;
        const float* s_wdev = s_w + 896;
        const float* s_bdev = s_w + 1792;
        const float* s_wsrv = s_w + 1856;
        const float* s_bsrv = s_w + 2048;
        for (int idx = tid; idx < 4096; idx += NT) {
            int i = idx >> 6, j = idx & 63;
            float acc;
            if (i < 63) {
                acc = s_bdev[j];
                const float* o = s_obs + i * 14;
#pragma unroll
                for (int k = 0; k < 14; k++)
                    acc = fmaf(o[k], s_wdev[k * 64 + j], acc);
            } else {
                acc = s_bsrv[j];
                acc = fmaf(so0, s_wsrv[j], acc);
                acc = fmaf(so1, s_wsrv[64 + j], acc);
                acc = fmaf(so2, s_wsrv[128 + j], acc);
            }
            s_h[i * ST + (j ^ (i & 4))] = f2tf(fmaxf(acc, 0.0f));
        }
    }
    __syncthreads();

    // ---- cache adjacency A-fragments in registers; stage W1 ----
    unsigned af[8][4];
    {
        const float* A0 = s_aux + r0 * ST;
        const float* A1 = s_aux + r1 * ST;
        const int ca = tig ^ x4;
#pragma unroll
        for (int ks = 0; ks < 8; ks++) {
            af[ks][0] = __float_as_uint(A0[ca + 8 * ks]);
            af[ks][1] = __float_as_uint(A1[ca + 8 * ks]);
            af[ks][2] = __float_as_uint(A0[(ca ^ 4) + 8 * ks]);
            af[ks][3] = __float_as_uint(A1[(ca ^ 4) + 8 * ks]);
        }
    }
    stage_w(s_w, W1, 64, 0, tid);
    __syncthreads();

    const float dr0 = s_d[r0], dr1 = s_d[r1];
    const int pc0 = 2 * tig;   // logical col base of C frags

    // ---- 3 GCN layers: h' = relu(D·A·(D·(h@W)) + b) ----
    const float* stage_src[3] = {W2, W3, Wf1};
    const int    stage_str[3] = {64, 64, 128};
#pragma unroll 1
    for (int L = 0; L < 3; L++) {
        float c[8][4];
        // GEMM-A: g = h @ W_L (A = own rows of s_h)
        gemm_ss(s_h, s_w, rb, gid, tig, c);
        // epilogue: g' = d_k * g, tf32, into own rows of s_h (warp-private, no race)
#pragma unroll
        for (int nt = 0; nt < 8; nt++) {
            int pc = ((nt << 3) + pc0) ^ x4;
            *(float2*)&s_h[r0 * ST + pc] = make_float2(f2tf(c[nt][0] * dr0), f2tf(c[nt][1] * dr0));
            *(float2*)&s_h[r1 * ST + pc] = make_float2(f2tf(c[nt][2] * dr1), f2tf(c[nt][3] * dr1));
        }
        __syncthreads();   // g' visible; all s_w reads done

        // GEMM-B: C2 = A(binary, regs) @ g' ; concurrently stage next weights
        gemm_rs(af, s_h, gid, tig, c);
        stage_w(s_w, stage_src[L], stage_str[L], 0, tid);
        __syncthreads();   // all g' reads done; next W visible

        // epilogue: h' = relu(d_i*C2 + b_L), tf32, own rows
#pragma unroll
        for (int nt = 0; nt < 8; nt++) {
            int j = (nt << 3) + pc0;
            float bx = s_h[j * ST + 64 + L];
            float by = s_h[(j + 1) * ST + 64 + L];
            int pc = j ^ x4;
            *(float2*)&s_h[r0 * ST + pc] =
                make_float2(f2tf(fmaxf(fmaf(dr0, c[nt][0], bx), 0.0f)),
                            f2tf(fmaxf(fmaf(dr0, c[nt][1], by), 0.0f)));
            *(float2*)&s_h[r1 * ST + pc] =
                make_float2(f2tf(fmaxf(fmaf(dr1, c[nt][2], bx), 0.0f)),
                            f2tf(fmaxf(fmaf(dr1, c[nt][3], by), 0.0f)));
        }
        __syncwarp();      // own rows re-read by same warp's next GEMM-A
    }
    __syncthreads();       // full h needed by mean / head B-reads

    // ---- dev_mean; stage Wf1 chunk1 into s_aux ----
    if (tid < 64) {
        float s = 0.0f;
#pragma unroll 7
        for (int r = 0; r < 63; r++) s += s_h[r * ST + (tid ^ (r & 4))];
        s_mean[tid] = s * (1.0f / 63.0f);
    }
    stage_w(s_aux, Wf1, 128, 64, tid);
    __syncthreads();

    // ---- shared head vector: bf1 + mean@Wf1[64:128] + srv@Wf1[128:192] ----
    {
        float acc = bf1[tid];
#pragma unroll 4
        for (int k = 0; k < 64; k++) {
            float srv = s_h[63 * ST + (k ^ 4)];
            acc = fmaf(s_mean[k], Wf1[(64 + k) * 128 + tid], acc);
            acc = fmaf(srv,       Wf1[(128 + k) * 128 + tid], acc);
        }
        s_sh[tid] = acc;
    }
    __syncthreads();

    // ---- head: two 64-col chunks, fully register-resident epilogue ----
    float p0 = 0.0f, p1 = 0.0f;
#pragma unroll 1
    for (int c2 = 0; c2 < 2; c2++) {
        float c[8][4];
        gemm_ss(s_h, (c2 ? s_aux : s_w), rb, gid, tig, c);
#pragma unroll
        for (int nt = 0; nt < 8; nt++) {
            int col = (c2 << 6) + (nt << 3) + pc0;
            float2 sh = *(const float2*)&s_sh[col];
            float2 w2 = *(const float2*)&s_w2[col];
            p0 = fmaf(fmaxf(c[nt][0] + sh.x, 0.0f), w2.x, p0);
            p0 = fmaf(fmaxf(c[nt][1] + sh.y, 0.0f), w2.y, p0);
            p1 = fmaf(fmaxf(c[nt][2] + sh.x, 0.0f), w2.x, p1);
            p1 = fmaf(fmaxf(c[nt][3] + sh.y, 0.0f), w2.y, p1);
        }
    }

    p0 += __shfl_xor_sync(0xffffffffu, p0, 1, 4);
    p0 += __shfl_xor_sync(0xffffffffu, p0, 2, 4);
    p1 += __shfl_xor_sync(0xffffffffu, p1, 1, 4);
    p1 += __shfl_xor_sync(0xffffffffu, p1, 2, 4);
    if (tig == 0) {
        out[(size_t)b * 63 + r0] = p0 + bf2v;
        if (r1 < 63) out[(size_t)b * 63 + r1] = p1 + bf2v;
    }
}

extern "C" void kernel_launch(void* const* d_in, const int* in_sizes, int n_in,
                              void* d_out, int out_size)
{
    const float* device_obs = (const float*)d_in[0];
    const float* server_obs = (const float*)d_in[1];
    const float* adjacency  = (const float*)d_in[2];
    const float* W_dev = (const float*)d_in[3];
    const float* b_dev = (const float*)d_in[4];
    const float* W_srv = (const float*)d_in[5];
    const float* b_srv = (const float*)d_in[6];
    const float* W1 = (const float*)d_in[7];
    const float* b1 = (const float*)d_in[8];
    const float* W2 = (const float*)d_in[9];
    const float* b2 = (const float*)d_in[10];
    const float* W3 = (const float*)d_in[11];
    const float* b3 = (const float*)d_in[12];
    const float* Wf1 = (const float*)d_in[13];
    const float* bf1 = (const float*)d_in[14];
    const float* Wf2 = (const float*)d_in[15];
    const float* bf2 = (const float*)d_in[16];

    const int B = in_sizes[0] / (63 * 14);
    const size_t smem = (3 * 64 * ST + 64 + 64 + 128 + 128) * sizeof(float);
    cudaFuncSetAttribute(pgcn_kernel, cudaFuncAttributeMaxDynamicSharedMemorySize, (int)smem);
    pgcn_kernel<<<B, NT, smem>>>(
        device_obs, server_obs, adjacency,
        W_dev, b_dev, W_srv, b_srv,
        W1, b1, W2, b2, W3, b3,
        Wf1, bf1, Wf2, bf2,
        (float*)d_out);
}